// round 7
// baseline (speedup 1.0000x reference)
#include <cuda_runtime.h>
#include <math.h>

typedef unsigned long long u64;

#define BATCH 64
#define H 224
#define W 224
#define NPAIR 192            // BATCH*3

// Device scratch (no allocation allowed)
__device__ float g_feat[BATCH * 75];

// Column masks for K=11 (stride 11, 128-bit mask in 2x u64)
constexpr u64 colmask_lo(int c) {
    u64 m = 0;
    for (int r = 0; r < 11; r++) { int p = r * 11 + c; if (p < 64) m |= 1ull << p; }
    return m;
}
constexpr u64 colmask_hi(int c) {
    u64 m = 0;
    for (int r = 0; r < 11; r++) { int p = r * 11 + c; if (p >= 64) m |= 1ull << (p - 64); }
    return m;
}
constexpr u64 NOTC0_LO  = ~colmask_lo(0);
constexpr u64 NOTC0_HI  = ~colmask_hi(0);
constexpr u64 NOTC10_LO = ~colmask_lo(10);
constexpr u64 NOTC10_HI = ~colmask_hi(10);

// 128-bit neighbor expansion (stride 11)
template <int K>
__device__ __forceinline__ void expand128(u64 clo, u64 chi, u64& glo, u64& ghi) {
    u64 l1lo = clo << 1;
    u64 l1hi = (chi << 1) | (clo >> 63);
    u64 r1lo = (clo >> 1) | (chi << 63);
    u64 r1hi = chi >> 1;
    if (K == 11) {
        l1lo &= NOTC0_LO;  l1hi &= NOTC0_HI;
        r1lo &= NOTC10_LO; r1hi &= NOTC10_HI;
    }
    u64 uplo = clo << 11;
    u64 uphi = (chi << 11) | (clo >> 53);
    u64 dnlo = (clo >> 11) | (chi << 53);
    u64 dnhi = chi >> 11;
    glo = l1lo | r1lo | uplo | dnlo;
    ghi = l1hi | r1hi | uphi | dnhi;
}

// ---------------------------------------------------------------------------
// One 512-thread block handles one (K, b, ch) entirely; reads NHWC directly,
// accumulates in shared, finalizes inline.
// ---------------------------------------------------------------------------
template <int K>
__device__ __forceinline__ void patch_seg(const float* __restrict__ in, int pair,
                                          int* sh_hist, int* sh_sums) {
    constexpr int ROWS = (H + K - 1) / K;
    constexpr int COLS = (W + K - 1) / K;
    constexpr int P    = ROWS * COLS;
    constexpr int PADT = (ROWS * K - H) / 2;   // 0 except K=11 (3)
    constexpr int PADL = (COLS * K - W) / 2;
    constexpr int KK   = K * K;
    constexpr int STRIDE = (K <= 7) ? 8 : 11;
    constexpr bool WIDE   = (K > 7);
    constexpr bool NOPAD  = (K == 7);          // 224 = 32*7 exact
    constexpr bool HASNEG = (K == 11);         // only K=11 pads top/left

    const int b  = pair / 3;
    const int ch = pair % 3;
    const float* __restrict__ img = in + b * (H * W * 3) + ch;

    const int tid = threadIdx.x;
    for (int i = tid; i < KK + 1; i += 512) sh_hist[i] = 0;
    if (tid < 3) sh_sums[tid] = 0;
    __syncthreads();

    int t_nc = 0, t_pc = 0, t_ma = 0;

    for (int pidx = tid; pidx < P; pidx += 512) {
        const int i  = pidx / COLS;
        const int j  = pidx - i * COLS;
        const int r0 = i * K - PADT;
        const int c0 = j * K - PADL;

        const float center = __ldg(img + ((r0 + K / 2) * W + (c0 + K / 2)) * 3);
        bool interior = true;
        if (!NOPAD)
            interior = (!HASNEG || ((r0 >= 0) & (c0 >= 0))) &
                       (r0 + K <= H) & (c0 + K <= W);

        u64 mlo = 0, mhi = 0;
        if (interior) {
            const float* base = img + (r0 * W + c0) * 3;
            #pragma unroll
            for (int dy = 0; dy < K; dy++) {
                unsigned m = 0;
                #pragma unroll
                for (int dx = 0; dx < K; dx++) {
                    float v = __ldg(base + (dy * W + dx) * 3);   // imm offsets
                    if (fabsf(v - center) <= (float)K) m |= (1u << dx);
                }
                int p = dy * STRIDE;
                if (p < 64) {
                    mlo |= (u64)m << p;
                    if (p + K > 64) mhi |= (u64)m >> (64 - p);
                } else {
                    mhi |= (u64)m << (p - 64);
                }
            }
        } else {
            #pragma unroll
            for (int dy = 0; dy < K; dy++) {
                const int r = r0 + dy;
                unsigned m = 0;
                #pragma unroll
                for (int dx = 0; dx < K; dx++) {
                    const int c = c0 + dx;
                    bool ok = HASNEG ? ((unsigned)r < (unsigned)H && (unsigned)c < (unsigned)W)
                                     : (r < H && c < W);
                    float v = ok ? __ldg(img + (r * W + c) * 3) : 0.0f;
                    if (fabsf(v - center) <= (float)K) m |= (1u << dx);
                }
                int p = dy * STRIDE;
                if (p < 64) {
                    mlo |= (u64)m << p;
                    if (p + K > 64) mhi |= (u64)m >> (64 - p);
                } else {
                    mhi |= (u64)m << (p - 64);
                }
            }
        }

        const int ones = __popcll(mlo) + __popcll(mhi);
        int nc, best = KK - ones;

        if (!WIDE) {
            const u64 m = mlo;
            u64 neigh = (m << 1) | (m >> 1) | (m << 8) | (m >> 8);
            u64 iso = m & ~neigh;
            nc = __popcll(iso);
            u64 rem = m ^ iso;
            while (rem) {
                u64 cur = rem & (0ull - rem);
                while (true) {
                    u64 g1 = (cur | (cur << 1) | (cur >> 1) | (cur << 8) | (cur >> 8)) & rem;
                    u64 g2 = (g1 | (g1 << 1) | (g1 >> 1) | (g1 << 8) | (g1 >> 8)) & rem;
                    if (g2 == cur) break;
                    cur = g2;
                }
                int a = __popcll(cur);
                if (a > best) best = a;
                rem ^= cur;
                nc++;
            }
        } else {
            u64 nlo, nhi;
            expand128<K>(mlo, mhi, nlo, nhi);
            u64 isolo = mlo & ~nlo, isohi = mhi & ~nhi;
            nc = __popcll(isolo) + __popcll(isohi);
            u64 rlo = mlo ^ isolo, rhi = mhi ^ isohi;
            while (rlo | rhi) {
                u64 clo, chi;
                if (rlo) { clo = rlo & (0ull - rlo); chi = 0; }
                else     { clo = 0; chi = rhi & (0ull - rhi); }
                while (true) {
                    u64 elo, ehi, g1lo, g1hi, g2lo, g2hi;
                    expand128<K>(clo, chi, elo, ehi);
                    g1lo = (clo | elo) & rlo;
                    g1hi = (chi | ehi) & rhi;
                    expand128<K>(g1lo, g1hi, elo, ehi);
                    g2lo = (g1lo | elo) & rlo;
                    g2hi = (g1hi | ehi) & rhi;
                    if (g2lo == clo && g2hi == chi) break;
                    clo = g2lo; chi = g2hi;
                }
                int a = __popcll(clo) + __popcll(chi);
                if (a > best) best = a;
                rlo ^= clo; rhi ^= chi;
                nc++;
            }
        }

        // Warp-aggregated histogram add
        {
            unsigned act   = __activemask();
            unsigned peers = __match_any_sync(act, ones);
            int lane = tid & 31;
            if (lane == (__ffs(peers) - 1))
                atomicAdd(&sh_hist[ones], __popc(peers));
        }
        t_nc += nc;
        t_pc += ((float)ones / (float)KK >= 0.59275f) ? 1 : 0;
        t_ma += best;
    }

    // Warp-level reduce, then one shared atomic per warp
    __syncwarp();
    t_nc = __reduce_add_sync(0xffffffffu, t_nc);
    t_pc = __reduce_add_sync(0xffffffffu, t_pc);
    t_ma = __reduce_add_sync(0xffffffffu, t_ma);
    if ((tid & 31) == 0) {
        atomicAdd(&sh_sums[0], t_nc);
        atomicAdd(&sh_sums[1], t_pc);
        atomicAdd(&sh_sums[2], t_ma);
    }
    __syncthreads();

    if (tid == 0) {
        const float fP = (float)P;
        float fd = 0.0f, m = 0.0f, m2 = 0.0f;
        for (int q = 0; q < KK; q++) {     // bin KK (fully on) dropped (tf bincount)
            float p = (float)sh_hist[q] / fP;
            float n = (float)(q + 1);
            fd += p / n;
            m  += p * n;
            m2 += p * p * n;
        }
        float lac = (m2 - m * m) / (m * m);
        int acn  = sh_sums[0] / P;
        int acp  = sh_sums[1] / P;
        int acma = sh_sums[2] / P;

        constexpr int kidx = (K - 3) / 2;
        const int o = ((b * 5) * 5 + kidx) * 3 + ch;
        g_feat[o + 0 * 15] = (float)acn;
        g_feat[o + 1 * 15] = (float)acp;
        g_feat[o + 2 * 15] = (float)acma;
        g_feat[o + 3 * 15] = lac;
        g_feat[o + 4 * 15] = fd;
    }
}

__global__ __launch_bounds__(512) void patch_all_kernel(const float* __restrict__ in) {
    __shared__ int sh_hist[122];
    __shared__ int sh_sums[3];
    const int seg  = blockIdx.x / NPAIR;   // 0:k11 1:k9 2:k7 3:k5 4:k3
    const int pair = blockIdx.x % NPAIR;
    if (seg == 0)      patch_seg<11>(in, pair, sh_hist, sh_sums);
    else if (seg == 1) patch_seg<9>(in, pair, sh_hist, sh_sums);
    else if (seg == 2) patch_seg<7>(in, pair, sh_hist, sh_sums);
    else if (seg == 3) patch_seg<5>(in, pair, sh_hist, sh_sums);
    else               patch_seg<3>(in, pair, sh_hist, sh_sums);
}

// ---------------------------------------------------------------------------
// Bilinear resize via smem pre-lerped rows, float4 LDS
// ---------------------------------------------------------------------------
#define RCHUNK 28
#define YBLKS (H / RCHUNK)   // 8
#define WC (W * 3)           // 672

__global__ __launch_bounds__(256) void resize_kernel(float* __restrict__ out) {
    __shared__ float feat[75];
    __shared__ __align__(16) float hrow[5 * WC];   // 3360
    __shared__ float s_fy[RCHUNK];
    __shared__ int   s_y0[RCHUNK], s_y1[RCHUNK];

    const int b   = blockIdx.x / YBLKS;
    const int yc  = blockIdx.x % YBLKS;
    const int tid = threadIdx.x;

    if (tid < 75) feat[tid] = g_feat[b * 75 + tid];
    if (tid >= 96 && tid < 96 + RCHUNK) {
        int y = yc * RCHUNK + (tid - 96);
        float cy = ((float)y + 0.5f) * (5.0f / 224.0f) - 0.5f;
        float fl = floorf(cy);
        int y0 = (int)fl;
        float fy = cy - fl;
        int y0c = max(y0, 0), y1c = min(y0 + 1, 4);
        s_fy[tid - 96] = fy;
        s_y0[tid - 96] = y0c * WC;
        s_y1[tid - 96] = y1c * WC;
    }
    __syncthreads();

    for (int i = tid; i < 5 * WC; i += 256) {
        int r  = i / WC;
        int xc = i - r * WC;
        int x  = xc / 3;
        int ch = xc - x * 3;
        float cx = ((float)x + 0.5f) * (5.0f / 224.0f) - 0.5f;
        float fl = floorf(cx);
        int x0 = (int)fl;
        float fx = cx - fl;
        int x0c = max(x0, 0), x1c = min(x0 + 1, 4);
        float a  = feat[(r * 5 + x0c) * 3 + ch];
        float bb = feat[(r * 5 + x1c) * 3 + ch];
        hrow[i] = a + fx * (bb - a);
    }
    __syncthreads();

    float4* o4 = (float4*)(out + b * (H * WC) + yc * (RCHUNK * WC));
    const int N4 = RCHUNK * WC / 4;   // 4704
    for (int i = tid; i < N4; i += 256) {
        int yl = i / (WC / 4);
        int x4 = i - yl * (WC / 4);
        const float4 a  = *(const float4*)&hrow[s_y0[yl] + 4 * x4];
        const float4 bb = *(const float4*)&hrow[s_y1[yl] + 4 * x4];
        const float fy = s_fy[yl];
        float4 v;
        v.x = a.x + fy * (bb.x - a.x);
        v.y = a.y + fy * (bb.y - a.y);
        v.z = a.z + fy * (bb.z - a.z);
        v.w = a.w + fy * (bb.w - a.w);
        o4[i] = v;
    }
}

// ---------------------------------------------------------------------------
extern "C" void kernel_launch(void* const* d_in, const int* in_sizes, int n_in,
                              void* d_out, int out_size) {
    const float* in = (const float*)d_in[0];
    float* out = (float*)d_out;

    patch_all_kernel<<<5 * NPAIR, 512>>>(in);
    resize_kernel<<<BATCH * YBLKS, 256>>>(out);
}